// round 11
// baseline (speedup 1.0000x reference)
#include <cuda_runtime.h>
#include <cuda_fp16.h>
#include <cstdint>

// Fused 3D windowed attention block — fp16 tensor-core, minimal splits.
// R11: CTA = 2 windows (512 thr, 16 warps), warp tile 64m x 16n (B traffic halved),
//      Q register-resident, Y hi-only over K region (self-conflict-free), conv 2-term.

#define D0 30
#define H0 62
#define W0 126
#define MTOT (30*62*126)

#define AST 136     // halves/row: x hi (128 rows = 2 windows), also K/Y stride
#define KST 136
#define VTST 72     // halves/row: Vt (256 rows = 2 windows x 128 dims, 64 keys + pad)

#define SM_A    0          // 36864: x hi; later Vt lo (rows 256, stride 72)
#define SM_K    36864      // 34816: K hi (rows 128 = win*64+key); later Y hi
#define SM_VTHI 71680      // 36864: Vt hi
#define SM_BIAS 108544     // 384 f32
#define SMEM_BYTES 110080

// weights in B-fragment order: [mat 0..3][wn 0..7][kk 0..7][lane 0..31] x uint4
// mats: 0=Q, 1=K, 2=V, 3=conv
__device__ __align__(256) uint4 g_bh4[4 * 8 * 8 * 32];
__device__ __align__(256) uint4 g_bl4[4 * 8 * 8 * 32];

__device__ __forceinline__ uint32_t smem_u32(const void* p) {
    uint32_t a;
    asm("{ .reg .u64 t; cvta.to.shared.u64 t, %1; cvt.u32.u64 %0, t; }"
        : "=r"(a) : "l"(p));
    return a;
}
__device__ __forceinline__ void ldsm4(uint32_t (&r)[4], uint32_t addr) {
    asm volatile("ldmatrix.sync.aligned.m8n8.x4.shared.b16 {%0,%1,%2,%3}, [%4];"
                 : "=r"(r[0]), "=r"(r[1]), "=r"(r[2]), "=r"(r[3]) : "r"(addr));
}
__device__ __forceinline__ void mma16816(float (&d)[4], const uint32_t (&a)[4],
                                         uint32_t b0, uint32_t b1) {
    asm volatile("mma.sync.aligned.m16n8k16.row.col.f32.f16.f16.f32 "
                 "{%0,%1,%2,%3}, {%4,%5,%6,%7}, {%8,%9}, {%0,%1,%2,%3};"
                 : "+f"(d[0]), "+f"(d[1]), "+f"(d[2]), "+f"(d[3])
                 : "r"(a[0]), "r"(a[1]), "r"(a[2]), "r"(a[3]), "r"(b0), "r"(b1));
}
__device__ __forceinline__ uint32_t h2u(__half a, __half b) {
    __half2 p = __halves2half2(a, b);
    return *(uint32_t*)&p;
}
__device__ __forceinline__ uint32_t packf16(float a, float b) {
    __half2 p = __floats2half2_rn(a, b);
    return *(uint32_t*)&p;
}
__device__ __forceinline__ uint32_t splitf16(float a, float b, uint32_t& lo) {
    __half h0 = __float2half_rn(a), h1 = __float2half_rn(b);
    __half l0 = __float2half_rn(a - __half2float(h0));
    __half l1 = __float2half_rn(b - __half2float(h1));
    lo = h2u(l0, l1);
    return h2u(h0, h1);
}
__device__ __forceinline__ void split1h(char* hiB, char* loB, int off_h, float v) {
    __half h = __float2half_rn(v);
    __half l = __float2half_rn(v - __half2float(h));
    *(__half*)(hiB + 2 * off_h) = h;
    *(__half*)(loB + 2 * off_h) = l;
}

// 64x16x128 warp GEMM, 2-term fp16 (A hi-only from smem, B hi/lo from gmem frags)
__device__ __forceinline__ void gemm2_64(uint32_t aBase,
                                         const uint4* __restrict__ bh,
                                         const uint4* __restrict__ bl,
                                         int lane, int wm, float acc[4][2][4]) {
    const int r8 = lane & 7, g = lane >> 3;
    const uint32_t aoff = (uint32_t)(((wm * 64 + r8 + 8 * (g & 1)) * AST + 8 * (g >> 1)) * 2);
    #pragma unroll
    for (int kk = 0; kk < 8; ++kk) {
        uint4 BH = __ldg(bh + kk * 32);
        uint4 BL = __ldg(bl + kk * 32);
        #pragma unroll
        for (int mtp = 0; mtp < 2; ++mtp) {
            uint32_t a0[4], a1[4];
            uint32_t o = aoff + (uint32_t)(((2 * mtp) * 16 * AST + kk * 16) * 2);
            ldsm4(a0, aBase + o);
            ldsm4(a1, aBase + o + (uint32_t)(16 * AST * 2));
            mma16816(acc[2 * mtp][0],     a0, BH.x, BH.y);
            mma16816(acc[2 * mtp][0],     a0, BL.x, BL.y);
            mma16816(acc[2 * mtp][1],     a0, BH.z, BH.w);
            mma16816(acc[2 * mtp][1],     a0, BL.z, BL.w);
            mma16816(acc[2 * mtp + 1][0], a1, BH.x, BH.y);
            mma16816(acc[2 * mtp + 1][0], a1, BL.x, BL.y);
            mma16816(acc[2 * mtp + 1][1], a1, BH.z, BH.w);
            mma16816(acc[2 * mtp + 1][1], a1, BL.z, BL.w);
        }
    }
}

// ---------------- prep: weights -> fp16 hi/lo B-fragment layout ----------------
__global__ void prep_weights(const float* __restrict__ qkv_w,
                             const float* __restrict__ conv_w)
{
    int tid = blockIdx.x * 256 + threadIdx.x;    // 0..8191
    int lane = tid & 31;
    int kk   = (tid >> 5) & 7;
    int wn   = (tid >> 8) & 7;
    int mat  = tid >> 11;
    const float* W = (mat < 3) ? (qkv_w + mat * 16384) : conv_w;

    uint32_t hi[4], lo[4];
    #pragma unroll
    for (int r = 0; r < 4; ++r) {
        int n = wn * 16 + (r >> 1) * 8 + (lane >> 2);
        int k = kk * 16 + (r & 1) * 8 + 2 * (lane & 3);
        float v0 = W[n * 128 + k];
        float v1 = W[n * 128 + k + 1];
        hi[r] = splitf16(v0, v1, lo[r]);
    }
    g_bh4[tid] = make_uint4(hi[0], hi[1], hi[2], hi[3]);
    g_bl4[tid] = make_uint4(lo[0], lo[1], lo[2], lo[3]);
}

// ---------------- main kernel ----------------
__global__ void __launch_bounds__(512, 2)
fused_window_attn_mma(const float* __restrict__ x,
                      const float* __restrict__ qkv_b,
                      const float* __restrict__ conv_b,
                      float* __restrict__ out)
{
    extern __shared__ char smemc[];
    const uint32_t sb = smem_u32(smemc);
    float* biasS = (float*)(smemc + SM_BIAS);

    const int t    = threadIdx.x;
    const int wid  = t >> 5;
    const int lane = t & 31;
    const int wm = wid >> 3;     // window within CTA (0..1)
    const int wn = wid & 7;      // 16-col slice / head
    const int bi = blockIdx.x;

    // ---- phase 1: gather 2 windows -> A hi (rows = win*64 + l), bias ----
    #pragma unroll
    for (int it = 0; it < 16; ++it) {
        int idx = t + 512 * it;        // 0..8191
        int win = idx >> 12;
        int l   = idx & 63;
        int cp  = (idx >> 6) & 63;
        int wg  = 2 * bi + win;
        int gz = 4 * (wg >> 9) + (l >> 4);
        int gy = 4 * ((wg >> 5) & 15) + ((l >> 2) & 3);
        int gx = 4 * (wg & 31) + (l & 3);
        float v0 = 0.f, v1 = 0.f;
        if (gz < D0 && gy < H0 && gx < W0) {
            size_t base = (size_t)(gz * H0 + gy) * W0 + gx;
            v0 = x[(size_t)(2 * cp) * MTOT + base];
            v1 = x[(size_t)(2 * cp + 1) * MTOT + base];
        }
        *(uint32_t*)(smemc + SM_A + ((win * 64 + l) * AST + 2 * cp) * 2) = packf16(v0, v1);
    }
    if (t < 384) biasS[t] = qkv_b[t];
    __syncthreads();

    const int fragbase = wn * 8 * 32 + lane;
    const uint4* bhQ = g_bh4 + 0 * 2048 + fragbase;
    const uint4* blQ = g_bl4 + 0 * 2048 + fragbase;
    const uint4* bhK = g_bh4 + 1 * 2048 + fragbase;
    const uint4* blK = g_bl4 + 1 * 2048 + fragbase;
    const uint4* bhV = g_bh4 + 2 * 2048 + fragbase;
    const uint4* blV = g_bl4 + 2 * 2048 + fragbase;
    const uint4* bhC = g_bh4 + 3 * 2048 + fragbase;
    const uint4* blC = g_bl4 + 3 * 2048 + fragbase;

    const int erow = wm * 64 + (lane >> 2);       // +mt*16, +8
    const int ecol = wn * 16 + 2 * (lane & 3);    // +nt*8, +1

    // ---- Q GEMM (result held as fp16 A-fragments in registers) ----
    uint32_t qh[4][4];
    {
        float acc[4][2][4] = {};
        gemm2_64(sb + SM_A, bhQ, blQ, lane, wm, acc);
        #pragma unroll
        for (int mt = 0; mt < 4; ++mt)
            #pragma unroll
            for (int nt = 0; nt < 2; ++nt) {
                int col = ecol + nt * 8;
                float2 bv = *(const float2*)(biasS + col);
                qh[mt][2 * nt]     = packf16(acc[mt][nt][0] + bv.x, acc[mt][nt][1] + bv.y);
                qh[mt][2 * nt + 1] = packf16(acc[mt][nt][2] + bv.x, acc[mt][nt][3] + bv.y);
            }
    }

    // ---- K GEMM -> K hi smem (rows win*64+key) ----
    {
        float acc[4][2][4] = {};
        gemm2_64(sb + SM_A, bhK, blK, lane, wm, acc);
        #pragma unroll
        for (int mt = 0; mt < 4; ++mt)
            #pragma unroll
            for (int nt = 0; nt < 2; ++nt) {
                int col = ecol + nt * 8;
                float2 bv = *(const float2*)(biasS + 128 + col);
                int r0 = erow + mt * 16;
                *(uint32_t*)(smemc + SM_K + (r0 * KST + col) * 2) =
                    packf16(acc[mt][nt][0] + bv.x, acc[mt][nt][1] + bv.y);
                *(uint32_t*)(smemc + SM_K + ((r0 + 8) * KST + col) * 2) =
                    packf16(acc[mt][nt][2] + bv.x, acc[mt][nt][3] + bv.y);
            }
    }

    // ---- V GEMM mainloop; epilogue writes Vt-lo over A (all A reads must finish) ----
    {
        float acc[4][2][4] = {};
        gemm2_64(sb + SM_A, bhV, blV, lane, wm, acc);
        __syncthreads();     // every warp done reading A
        #pragma unroll
        for (int mt = 0; mt < 4; ++mt)
            #pragma unroll
            for (int nt = 0; nt < 2; ++nt) {
                int d = ecol + nt * 8;
                float2 bv = *(const float2*)(biasS + 256 + d);
                int key = (lane >> 2) + mt * 16;
                int base0 = (wm * 128 + d)     * VTST;
                int base1 = (wm * 128 + d + 1) * VTST;
                split1h(smemc + SM_VTHI, smemc + SM_A, base0 + key,     acc[mt][nt][0] + bv.x);
                split1h(smemc + SM_VTHI, smemc + SM_A, base1 + key,     acc[mt][nt][1] + bv.y);
                split1h(smemc + SM_VTHI, smemc + SM_A, base0 + key + 8, acc[mt][nt][2] + bv.x);
                split1h(smemc + SM_VTHI, smemc + SM_A, base1 + key + 8, acc[mt][nt][3] + bv.y);
            }
    }
    __syncthreads();   // K + Vt visible

    // ---- attention: warp = (win=wm, head=wn), two 32-row passes ----
    const int head = wn;
    const int wg2 = 2 * bi + wm;
    const int bz = wg2 >> 9, by = (wg2 >> 5) & 15, bx = wg2 & 31;
    unsigned long long pm = 0ull;
    if (bz == 7 || by == 15 || bx == 31) {
        #pragma unroll
        for (int m = 0; m < 64; ++m) {
            bool p = (bz == 7 && (m >> 4) >= 2) ||
                     (by == 15 && ((m >> 2) & 3) >= 2) ||
                     (bx == 31 && (m & 3) >= 2);
            pm |= (unsigned long long)(p ? 1u : 0u) << m;
        }
    }

    const int r8 = lane & 7;
    const uint32_t koff = (uint32_t)(((wm * 64 + r8 + 8 * ((lane >> 4) & 1)) * KST
                                      + head * 16 + 8 * ((lane >> 3) & 1)) * 2);
    const uint32_t voff = (uint32_t)(((wm * 128 + head * 16 + r8 + 8 * ((lane >> 4) & 1)) * VTST
                                      + 8 * ((lane >> 3) & 1)) * 2);

    uint32_t yp[2][8];   // packed Y-hi per half: [h][mtl*4 + sp*2 + rhalf]

    #pragma unroll
    for (int h = 0; h < 2; ++h) {
        unsigned rp[2][2];
        #pragma unroll
        for (int mtl = 0; mtl < 2; ++mtl) {
            int m = h * 32 + mtl * 16 + (lane >> 2);
            rp[mtl][0] = (unsigned)(pm >> m) & 1u;
            rp[mtl][1] = (unsigned)(pm >> (m + 8)) & 1u;
        }
        float oacc[2][2][4] = {};
        float rsum[2][2] = {};

        #pragma unroll
        for (int g4 = 0; g4 < 4; ++g4) {
            uint32_t kh[4];
            ldsm4(kh, sb + SM_K + koff + (uint32_t)(g4 * 16 * KST * 2));

            float sacc[2][2][4] = {};
            #pragma unroll
            for (int mtl = 0; mtl < 2; ++mtl)
                #pragma unroll
                for (int s = 0; s < 2; ++s)
                    mma16816(sacc[mtl][s], qh[2 * h + mtl], kh[2 * s], kh[2 * s + 1]);

            uint32_t ph[2][4];
            #pragma unroll
            for (int s = 0; s < 2; ++s) {
                int k0 = g4 * 16 + s * 8 + 2 * (lane & 3);
                unsigned cp0 = (unsigned)(pm >> k0) & 1u;
                unsigned cp1 = (unsigned)(pm >> (k0 + 1)) & 1u;
                #pragma unroll
                for (int mtl = 0; mtl < 2; ++mtl) {
                    float e0 = (cp0 == rp[mtl][0]) ? __expf(0.25f * sacc[mtl][s][0]) : 0.f;
                    float e1 = (cp1 == rp[mtl][0]) ? __expf(0.25f * sacc[mtl][s][1]) : 0.f;
                    float e2 = (cp0 == rp[mtl][1]) ? __expf(0.25f * sacc[mtl][s][2]) : 0.f;
                    float e3 = (cp1 == rp[mtl][1]) ? __expf(0.25f * sacc[mtl][s][3]) : 0.f;
                    rsum[mtl][0] += e0 + e1;
                    rsum[mtl][1] += e2 + e3;
                    ph[mtl][2 * s]     = packf16(e0, e1);
                    ph[mtl][2 * s + 1] = packf16(e2, e3);
                }
            }

            uint32_t vh[4], vl[4];
            ldsm4(vh, sb + SM_VTHI + voff + (uint32_t)(g4 * 16 * 2));
            ldsm4(vl, sb + SM_A    + voff + (uint32_t)(g4 * 16 * 2));
            #pragma unroll
            for (int mtl = 0; mtl < 2; ++mtl)
                #pragma unroll
                for (int sp = 0; sp < 2; ++sp) {
                    mma16816(oacc[mtl][sp], ph[mtl], vh[2 * sp], vh[2 * sp + 1]);
                    mma16816(oacc[mtl][sp], ph[mtl], vl[2 * sp], vl[2 * sp + 1]);
                }
        }

        #pragma unroll
        for (int mtl = 0; mtl < 2; ++mtl)
            #pragma unroll
            for (int q = 0; q < 2; ++q) {
                rsum[mtl][q] += __shfl_xor_sync(0xFFFFFFFFu, rsum[mtl][q], 1);
                rsum[mtl][q] += __shfl_xor_sync(0xFFFFFFFFu, rsum[mtl][q], 2);
                rsum[mtl][q] = 1.0f / rsum[mtl][q];
            }
        #pragma unroll
        for (int mtl = 0; mtl < 2; ++mtl)
            #pragma unroll
            for (int sp = 0; sp < 2; ++sp) {
                yp[h][mtl * 4 + sp * 2]     = packf16(oacc[mtl][sp][0] * rsum[mtl][0],
                                                      oacc[mtl][sp][1] * rsum[mtl][0]);
                yp[h][mtl * 4 + sp * 2 + 1] = packf16(oacc[mtl][sp][2] * rsum[mtl][1],
                                                      oacc[mtl][sp][3] * rsum[mtl][1]);
            }
    }

    // store Y hi over K region: exactly the cells this warp (alone) read
    #pragma unroll
    for (int h = 0; h < 2; ++h)
        #pragma unroll
        for (int mtl = 0; mtl < 2; ++mtl)
            #pragma unroll
            for (int sp = 0; sp < 2; ++sp) {
                int row = wm * 64 + h * 32 + mtl * 16 + (lane >> 2);
                int col = head * 16 + sp * 8 + 2 * (lane & 3);
                *(uint32_t*)(smemc + SM_K + (row * KST + col) * 2)       = yp[h][mtl * 4 + sp * 2];
                *(uint32_t*)(smemc + SM_K + ((row + 8) * KST + col) * 2) = yp[h][mtl * 4 + sp * 2 + 1];
            }
    __syncthreads();   // Y ready for all warps

    // ---- conv GEMM (2-term: Y hi x W hi/lo) + scattered output ----
    {
        float acc[4][2][4] = {};
        gemm2_64(sb + SM_K, bhC, blC, lane, wm, acc);
        const int wg = 2 * bi + wm;
        const int z0v = 4 * (wg >> 9), y0v = 4 * ((wg >> 5) & 15), x0v = 4 * (wg & 31);
        #pragma unroll
        for (int mt = 0; mt < 4; ++mt) {
            int l0 = (lane >> 2) + mt * 16;
            int l1 = l0 + 8;
            int gz0 = z0v + (l0 >> 4), gy0 = y0v + ((l0 >> 2) & 3), gx0 = x0v + (l0 & 3);
            int gz1 = z0v + (l1 >> 4), gy1 = y0v + ((l1 >> 2) & 3), gx1 = x0v + (l1 & 3);
            bool ok0 = (gz0 < D0 && gy0 < H0 && gx0 < W0);
            bool ok1 = (gz1 < D0 && gy1 < H0 && gx1 < W0);
            size_t va0 = (size_t)(gz0 * H0 + gy0) * W0 + gx0;
            size_t va1 = (size_t)(gz1 * H0 + gy1) * W0 + gx1;
            #pragma unroll
            for (int nt = 0; nt < 2; ++nt) {
                int o = ecol + nt * 8;
                float2 cb = *(const float2*)(conv_b + o);
                if (ok0) {
                    out[(size_t)o * MTOT + va0]       = acc[mt][nt][0] + cb.x;
                    out[(size_t)(o + 1) * MTOT + va0] = acc[mt][nt][1] + cb.y;
                }
                if (ok1) {
                    out[(size_t)o * MTOT + va1]       = acc[mt][nt][2] + cb.x;
                    out[(size_t)(o + 1) * MTOT + va1] = acc[mt][nt][3] + cb.y;
                }
            }
        }
    }
}

extern "C" void kernel_launch(void* const* d_in, const int* in_sizes, int n_in,
                              void* d_out, int out_size)
{
    const float* x      = (const float*)d_in[0];
    const float* qkv_w  = (const float*)d_in[1];
    const float* qkv_b  = (const float*)d_in[2];
    const float* conv_w = (const float*)d_in[3];
    const float* conv_b = (const float*)d_in[4];
    float* out = (float*)d_out;

    prep_weights<<<32, 256>>>(qkv_w, conv_w);

    cudaFuncSetAttribute(fused_window_attn_mma,
                         cudaFuncAttributeMaxDynamicSharedMemorySize, SMEM_BYTES);

    fused_window_attn_mma<<<2048, 512, SMEM_BYTES>>>(x, qkv_b, conv_b, out);
}

// round 12
// speedup vs baseline: 1.8333x; 1.8333x over previous
#include <cuda_runtime.h>
#include <cuda_fp16.h>
#include <cstdint>

// Fused 3D windowed attention block — fp16 tensor-core, minimal splits.
// R12 = R10 + fused K/V GEMM (one A pass) + conv 2-term on Y-hi only.
// 1 window/CTA, 512 threads (16 warps = 2 wm x 8 wn), 2 CTAs/SM.

#define D0 30
#define H0 62
#define W0 126
#define MTOT (30*62*126)

#define AST 136     // halves/row, A & Y tiles (64 rows)
#define KST 136     // halves/row, K hi tile (64 rows)
#define VTST 72     // halves/row, Vt tiles (128 dim rows x 64 keys + pad)

#define SM_AHI  0          // x hi, later Y hi
#define SM_KHI  17408      // K hi
#define SM_VTHI 34816      // Vt hi
#define SM_VTLO 53248      // Vt lo
#define SM_BIAS 71680      // 384 f32
#define SMEM_BYTES 73216

// weights in B-fragment order: [mat 0..3][wn 0..7][kk 0..7][lane 0..31] x uint4
// mats: 0=Q, 1=K, 2=V, 3=conv
__device__ __align__(256) uint4 g_bh4[4 * 8 * 8 * 32];
__device__ __align__(256) uint4 g_bl4[4 * 8 * 8 * 32];

__device__ __forceinline__ uint32_t smem_u32(const void* p) {
    uint32_t a;
    asm("{ .reg .u64 t; cvta.to.shared.u64 t, %1; cvt.u32.u64 %0, t; }"
        : "=r"(a) : "l"(p));
    return a;
}
__device__ __forceinline__ void ldsm4(uint32_t (&r)[4], uint32_t addr) {
    asm volatile("ldmatrix.sync.aligned.m8n8.x4.shared.b16 {%0,%1,%2,%3}, [%4];"
                 : "=r"(r[0]), "=r"(r[1]), "=r"(r[2]), "=r"(r[3]) : "r"(addr));
}
__device__ __forceinline__ void mma16816(float (&d)[4], const uint32_t (&a)[4],
                                         uint32_t b0, uint32_t b1) {
    asm volatile("mma.sync.aligned.m16n8k16.row.col.f32.f16.f16.f32 "
                 "{%0,%1,%2,%3}, {%4,%5,%6,%7}, {%8,%9}, {%0,%1,%2,%3};"
                 : "+f"(d[0]), "+f"(d[1]), "+f"(d[2]), "+f"(d[3])
                 : "r"(a[0]), "r"(a[1]), "r"(a[2]), "r"(a[3]), "r"(b0), "r"(b1));
}
__device__ __forceinline__ uint32_t h2u(__half a, __half b) {
    __half2 p = __halves2half2(a, b);
    return *(uint32_t*)&p;
}
__device__ __forceinline__ uint32_t packf16(float a, float b) {
    __half2 p = __floats2half2_rn(a, b);
    return *(uint32_t*)&p;
}
__device__ __forceinline__ uint32_t splitf16(float a, float b, uint32_t& lo) {
    __half h0 = __float2half_rn(a), h1 = __float2half_rn(b);
    __half l0 = __float2half_rn(a - __half2float(h0));
    __half l1 = __float2half_rn(b - __half2float(h1));
    lo = h2u(l0, l1);
    return h2u(h0, h1);
}
__device__ __forceinline__ void split1h(char* hiB, char* loB, int off_h, float v) {
    __half h = __float2half_rn(v);
    __half l = __float2half_rn(v - __half2float(h));
    *(__half*)(hiB + 2 * off_h) = h;
    *(__half*)(loB + 2 * off_h) = l;
}

// ---------------- prep: weights -> fp16 hi/lo B-fragment layout ----------------
__global__ void prep_weights(const float* __restrict__ qkv_w,
                             const float* __restrict__ conv_w)
{
    int tid = blockIdx.x * 256 + threadIdx.x;    // 0..8191
    int lane = tid & 31;
    int kk   = (tid >> 5) & 7;
    int wn   = (tid >> 8) & 7;
    int mat  = tid >> 11;
    const float* W = (mat < 3) ? (qkv_w + mat * 16384) : conv_w;

    uint32_t hi[4], lo[4];
    #pragma unroll
    for (int r = 0; r < 4; ++r) {
        int n = wn * 16 + (r >> 1) * 8 + (lane >> 2);
        int k = kk * 16 + (r & 1) * 8 + 2 * (lane & 3);
        float v0 = W[n * 128 + k];
        float v1 = W[n * 128 + k + 1];
        hi[r] = splitf16(v0, v1, lo[r]);
    }
    g_bh4[tid] = make_uint4(hi[0], hi[1], hi[2], hi[3]);
    g_bl4[tid] = make_uint4(lo[0], lo[1], lo[2], lo[3]);
}

// ---------------- main kernel ----------------
__global__ void __launch_bounds__(512, 2)
fused_window_attn_mma(const float* __restrict__ x,
                      const float* __restrict__ qkv_b,
                      const float* __restrict__ conv_b,
                      float* __restrict__ out)
{
    extern __shared__ char smemc[];
    const uint32_t sb = smem_u32(smemc);
    float* biasS = (float*)(smemc + SM_BIAS);

    const int t    = threadIdx.x;
    const int wid  = t >> 5;
    const int lane = t & 31;
    const int wm = wid >> 3;
    const int wn = wid & 7;
    const int wi = blockIdx.x;
    const int bz = wi >> 9, by = (wi >> 5) & 15, bx = wi & 31;
    const int z0 = bz * 4, y0 = by * 4, x0 = bx * 4;

    // ---- phase 1: gather x -> A hi (fp16), bias ----
    #pragma unroll
    for (int it = 0; it < 8; ++it) {
        int idx = t + 512 * it;
        int l  = idx & 63;
        int cp = idx >> 6;
        int gz = z0 + (l >> 4);
        int gy = y0 + ((l >> 2) & 3);
        int gx = x0 + (l & 3);
        float v0 = 0.f, v1 = 0.f;
        if (gz < D0 && gy < H0 && gx < W0) {
            size_t base = (size_t)(gz * H0 + gy) * W0 + gx;
            v0 = x[(size_t)(2 * cp) * MTOT + base];
            v1 = x[(size_t)(2 * cp + 1) * MTOT + base];
        }
        *(uint32_t*)(smemc + SM_AHI + (l * AST + 2 * cp) * 2) = packf16(v0, v1);
    }
    if (t < 384) biasS[t] = qkv_b[t];
    __syncthreads();

    const uint32_t aHi = sb + SM_AHI;
    const int fragbase = wn * 8 * 32 + lane;
    const uint4* bhQ = g_bh4 + 0 * 2048 + fragbase;
    const uint4* blQ = g_bl4 + 0 * 2048 + fragbase;
    const uint4* bhK = g_bh4 + 1 * 2048 + fragbase;
    const uint4* blK = g_bl4 + 1 * 2048 + fragbase;
    const uint4* bhV = g_bh4 + 2 * 2048 + fragbase;
    const uint4* blV = g_bl4 + 2 * 2048 + fragbase;
    const uint4* bhC = g_bh4 + 3 * 2048 + fragbase;
    const uint4* blC = g_bl4 + 3 * 2048 + fragbase;

    const int r8 = lane & 7, g8 = lane >> 3;
    const uint32_t aoff = (uint32_t)(((wm * 32 + r8 + 8 * (g8 & 1)) * AST + 8 * (g8 >> 1)) * 2);

    const int erow = wm * 32 + (lane >> 2);
    const int ecol = wn * 16 + 2 * (lane & 3);

    // ---- fused K+V GEMMs (one A pass) ----
    {
        float accK[2][2][4] = {};
        float accV[2][2][4] = {};
        #pragma unroll
        for (int kk = 0; kk < 8; ++kk) {
            uint32_t ah[2][4];
            #pragma unroll
            for (int mt = 0; mt < 2; ++mt)
                ldsm4(ah[mt], aHi + aoff + (uint32_t)((mt * 16 * AST + kk * 16) * 2));
            {
                uint4 BH = __ldg(bhK + kk * 32);
                uint4 BL = __ldg(blK + kk * 32);
                #pragma unroll
                for (int mt = 0; mt < 2; ++mt) {
                    mma16816(accK[mt][0], ah[mt], BH.x, BH.y);
                    mma16816(accK[mt][0], ah[mt], BL.x, BL.y);
                    mma16816(accK[mt][1], ah[mt], BH.z, BH.w);
                    mma16816(accK[mt][1], ah[mt], BL.z, BL.w);
                }
            }
            {
                uint4 BH = __ldg(bhV + kk * 32);
                uint4 BL = __ldg(blV + kk * 32);
                #pragma unroll
                for (int mt = 0; mt < 2; ++mt) {
                    mma16816(accV[mt][0], ah[mt], BH.x, BH.y);
                    mma16816(accV[mt][0], ah[mt], BL.x, BL.y);
                    mma16816(accV[mt][1], ah[mt], BH.z, BH.w);
                    mma16816(accV[mt][1], ah[mt], BL.z, BL.w);
                }
            }
        }
        // K epilogue -> K hi smem
        #pragma unroll
        for (int mt = 0; mt < 2; ++mt)
            #pragma unroll
            for (int nt = 0; nt < 2; ++nt) {
                int col = ecol + nt * 8;
                float2 bv = *(const float2*)(biasS + 128 + col);
                int r0 = erow + mt * 16;
                *(uint32_t*)(smemc + SM_KHI + (r0 * KST + col) * 2) =
                    packf16(accK[mt][nt][0] + bv.x, accK[mt][nt][1] + bv.y);
                *(uint32_t*)(smemc + SM_KHI + ((r0 + 8) * KST + col) * 2) =
                    packf16(accK[mt][nt][2] + bv.x, accK[mt][nt][3] + bv.y);
            }
        // V epilogue -> Vt hi/lo smem (transposed)
        #pragma unroll
        for (int mt = 0; mt < 2; ++mt)
            #pragma unroll
            for (int nt = 0; nt < 2; ++nt) {
                int col = ecol + nt * 8;
                float2 bv = *(const float2*)(biasS + 256 + col);
                int r0 = erow + mt * 16;
                split1h(smemc + SM_VTHI, smemc + SM_VTLO, col * VTST + r0,           accV[mt][nt][0] + bv.x);
                split1h(smemc + SM_VTHI, smemc + SM_VTLO, (col + 1) * VTST + r0,     accV[mt][nt][1] + bv.y);
                split1h(smemc + SM_VTHI, smemc + SM_VTLO, col * VTST + r0 + 8,       accV[mt][nt][2] + bv.x);
                split1h(smemc + SM_VTHI, smemc + SM_VTLO, (col + 1) * VTST + r0 + 8, accV[mt][nt][3] + bv.y);
            }
    }

    // ---- Q GEMM (hi fragments stay in registers) ----
    uint32_t qh[2][4];
    {
        float acc[2][2][4] = {};
        #pragma unroll
        for (int kk = 0; kk < 8; ++kk) {
            uint4 BH = __ldg(bhQ + kk * 32);
            uint4 BL = __ldg(blQ + kk * 32);
            uint32_t ah[2][4];
            #pragma unroll
            for (int mt = 0; mt < 2; ++mt)
                ldsm4(ah[mt], aHi + aoff + (uint32_t)((mt * 16 * AST + kk * 16) * 2));
            #pragma unroll
            for (int mt = 0; mt < 2; ++mt) {
                mma16816(acc[mt][0], ah[mt], BH.x, BH.y);
                mma16816(acc[mt][0], ah[mt], BL.x, BL.y);
                mma16816(acc[mt][1], ah[mt], BH.z, BH.w);
                mma16816(acc[mt][1], ah[mt], BL.z, BL.w);
            }
        }
        #pragma unroll
        for (int mt = 0; mt < 2; ++mt)
            #pragma unroll
            for (int nt = 0; nt < 2; ++nt) {
                int col = ecol + nt * 8;
                float2 bv = *(const float2*)(biasS + col);
                qh[mt][2 * nt]     = packf16(acc[mt][nt][0] + bv.x, acc[mt][nt][1] + bv.y);
                qh[mt][2 * nt + 1] = packf16(acc[mt][nt][2] + bv.x, acc[mt][nt][3] + bv.y);
            }
    }
    __syncthreads();   // K/Vt visible; all A reads done

    // ---- attention, warp = (rowhalf wm, head wn) ----
    unsigned long long pm = 0ull;
    if (bz == 7 || by == 15 || bx == 31) {
        #pragma unroll
        for (int m = 0; m < 64; ++m) {
            bool p = (bz == 7 && (m >> 4) >= 2) ||
                     (by == 15 && ((m >> 2) & 3) >= 2) ||
                     (bx == 31 && (m & 3) >= 2);
            pm |= (unsigned long long)(p ? 1u : 0u) << m;
        }
    }
    const int head = wn;
    unsigned rp[2][2];
    #pragma unroll
    for (int mt = 0; mt < 2; ++mt) {
        int r0 = wm * 32 + mt * 16 + (lane >> 2);
        rp[mt][0] = (unsigned)(pm >> r0) & 1u;
        rp[mt][1] = (unsigned)(pm >> (r0 + 8)) & 1u;
    }

    const uint32_t koff = (uint32_t)(((r8 + 8 * ((lane >> 4) & 1)) * KST
                                      + head * 16 + 8 * ((lane >> 3) & 1)) * 2);
    const uint32_t voff = (uint32_t)(((head * 16 + r8 + 8 * ((lane >> 4) & 1)) * VTST
                                      + 8 * ((lane >> 3) & 1)) * 2);

    float oacc[2][2][4] = {};
    float rsum[2][2] = {};

    #pragma unroll
    for (int g4 = 0; g4 < 4; ++g4) {
        uint32_t kh[4];
        ldsm4(kh, sb + SM_KHI + koff + (uint32_t)(g4 * 16 * KST * 2));

        float sacc[2][2][4] = {};
        #pragma unroll
        for (int mt = 0; mt < 2; ++mt)
            #pragma unroll
            for (int s = 0; s < 2; ++s)
                mma16816(sacc[mt][s], qh[mt], kh[2 * s], kh[2 * s + 1]);

        uint32_t ph[2][4];
        #pragma unroll
        for (int s = 0; s < 2; ++s) {
            int k0 = g4 * 16 + s * 8 + 2 * (lane & 3);
            unsigned cp0 = (unsigned)(pm >> k0) & 1u;
            unsigned cp1 = (unsigned)(pm >> (k0 + 1)) & 1u;
            #pragma unroll
            for (int mt = 0; mt < 2; ++mt) {
                float e0 = (cp0 == rp[mt][0]) ? __expf(0.25f * sacc[mt][s][0]) : 0.f;
                float e1 = (cp1 == rp[mt][0]) ? __expf(0.25f * sacc[mt][s][1]) : 0.f;
                float e2 = (cp0 == rp[mt][1]) ? __expf(0.25f * sacc[mt][s][2]) : 0.f;
                float e3 = (cp1 == rp[mt][1]) ? __expf(0.25f * sacc[mt][s][3]) : 0.f;
                rsum[mt][0] += e0 + e1;
                rsum[mt][1] += e2 + e3;
                ph[mt][2 * s]     = packf16(e0, e1);
                ph[mt][2 * s + 1] = packf16(e2, e3);
            }
        }

        uint32_t vh[4], vl[4];
        ldsm4(vh, sb + SM_VTHI + voff + (uint32_t)(g4 * 16 * 2));
        ldsm4(vl, sb + SM_VTLO + voff + (uint32_t)(g4 * 16 * 2));
        #pragma unroll
        for (int mt = 0; mt < 2; ++mt)
            #pragma unroll
            for (int sp = 0; sp < 2; ++sp) {
                mma16816(oacc[mt][sp], ph[mt], vh[2 * sp], vh[2 * sp + 1]);
                mma16816(oacc[mt][sp], ph[mt], vl[2 * sp], vl[2 * sp + 1]);
            }
    }

    // quad-reduce row sums, normalize, store Y hi into A region (x is dead)
    #pragma unroll
    for (int mt = 0; mt < 2; ++mt)
        #pragma unroll
        for (int h = 0; h < 2; ++h) {
            rsum[mt][h] += __shfl_xor_sync(0xFFFFFFFFu, rsum[mt][h], 1);
            rsum[mt][h] += __shfl_xor_sync(0xFFFFFFFFu, rsum[mt][h], 2);
            rsum[mt][h] = 1.0f / rsum[mt][h];
        }
    #pragma unroll
    for (int mt = 0; mt < 2; ++mt)
        #pragma unroll
        for (int sp = 0; sp < 2; ++sp) {
            int col = head * 16 + sp * 8 + 2 * (lane & 3);
            int r0 = wm * 32 + mt * 16 + (lane >> 2);
            *(uint32_t*)(smemc + SM_AHI + (r0 * AST + col) * 2) =
                packf16(oacc[mt][sp][0] * rsum[mt][0], oacc[mt][sp][1] * rsum[mt][0]);
            *(uint32_t*)(smemc + SM_AHI + ((r0 + 8) * AST + col) * 2) =
                packf16(oacc[mt][sp][2] * rsum[mt][1], oacc[mt][sp][3] * rsum[mt][1]);
        }
    __syncthreads();   // Y tiles ready

    // ---- conv GEMM (2-term: Y hi x W hi/lo) + scattered output ----
    {
        float acc[2][2][4] = {};
        #pragma unroll
        for (int kk = 0; kk < 8; ++kk) {
            uint4 BH = __ldg(bhC + kk * 32);
            uint4 BL = __ldg(blC + kk * 32);
            uint32_t ah[2][4];
            #pragma unroll
            for (int mt = 0; mt < 2; ++mt)
                ldsm4(ah[mt], aHi + aoff + (uint32_t)((mt * 16 * AST + kk * 16) * 2));
            #pragma unroll
            for (int mt = 0; mt < 2; ++mt) {
                mma16816(acc[mt][0], ah[mt], BH.x, BH.y);
                mma16816(acc[mt][0], ah[mt], BL.x, BL.y);
                mma16816(acc[mt][1], ah[mt], BH.z, BH.w);
                mma16816(acc[mt][1], ah[mt], BL.z, BL.w);
            }
        }
        #pragma unroll
        for (int mt = 0; mt < 2; ++mt) {
            int m0 = erow + mt * 16;
            int m1 = m0 + 8;
            int gz0 = z0 + (m0 >> 4), gy0 = y0 + ((m0 >> 2) & 3), gx0 = x0 + (m0 & 3);
            int gz1 = z0 + (m1 >> 4), gy1 = y0 + ((m1 >> 2) & 3), gx1 = x0 + (m1 & 3);
            bool ok0 = (gz0 < D0 && gy0 < H0 && gx0 < W0);
            bool ok1 = (gz1 < D0 && gy1 < H0 && gx1 < W0);
            size_t va0 = (size_t)(gz0 * H0 + gy0) * W0 + gx0;
            size_t va1 = (size_t)(gz1 * H0 + gy1) * W0 + gx1;
            #pragma unroll
            for (int nt = 0; nt < 2; ++nt) {
                int o = ecol + nt * 8;
                float2 cb = *(const float2*)(conv_b + o);
                if (ok0) {
                    out[(size_t)o * MTOT + va0]       = acc[mt][nt][0] + cb.x;
                    out[(size_t)(o + 1) * MTOT + va0] = acc[mt][nt][1] + cb.y;
                }
                if (ok1) {
                    out[(size_t)o * MTOT + va1]       = acc[mt][nt][2] + cb.x;
                    out[(size_t)(o + 1) * MTOT + va1] = acc[mt][nt][3] + cb.y;
                }
            }
        }
    }
}

extern "C" void kernel_launch(void* const* d_in, const int* in_sizes, int n_in,
                              void* d_out, int out_size)
{
    const float* x      = (const float*)d_in[0];
    const float* qkv_b  = (const float*)d_in[2];
    const float* conv_b = (const float*)d_in[4];
    float* out = (float*)d_out;

    prep_weights<<<32, 256>>>((const float*)d_in[1], (const float*)d_in[3]);

    cudaFuncSetAttribute(fused_window_attn_mma,
                         cudaFuncAttributeMaxDynamicSharedMemorySize, SMEM_BYTES);

    fused_window_attn_mma<<<4096, 512, SMEM_BYTES>>>(x, qkv_b, conv_b, out);
}